// round 17
// baseline (speedup 1.0000x reference)
#include <cuda_runtime.h>
#include <cuda_fp16.h>
#include <cstdint>

// Problem constants (fixed by the dataset)
#define B_TOTAL   32768
#define N_IN      128
#define NLAYERS   8
#define WID       256
#define KK        16
#define T         64          // batch rows per block; lane carries a row PAIR (half2)
#define NTHREADS  1024
#define NWARPS    32
#define NBLOCKS   (B_TOTAL / T)          // 512
#define SPLIT     1408        // cols < SPLIT live in SMEM; cols >= SPLIT in global scratch
#define NCOLS_ALL 1920        // 128 + 7*256 (layer-7 out never re-gathered)
#define TBL       (NLAYERS * WID * KK)   // 32768 table entries

// SMEM layout (dynamic, 231,424 B total):
//   [0      , 180224) s_hist     : __half2 [1408][32]  (history, transposed, row pairs)
//   [180224 , 205824) table buf 0: idx 16K | wt(half) 8K | bias 1K  (25,600 B)
//   [205824 , 231424) table buf 1: same
#define OFF_TBL0   180224
#define TBLBUF     25600
#define TB_IDX     0
#define TB_WT      16384
#define TB_BIAS    24576
#define SMEM_BYTES (OFF_TBL0 + 2 * TBLBUF)

// Global scratch for evicted history cols [1408, 1920): [block][col'][32 pairs]
#define SC_COLS (NCOLS_ALL - SPLIT)      // 512
__device__ __half2 g_scratch[(size_t)NBLOCKS * SC_COLS * (T / 2)];   // 32 MB
// Preprocessed tables (built by prep_kernel each replay)
__device__ __half  g_wh  [TBL];          // weights as plain half (16 per w = 32B, vector-loaded)
__device__ int     g_idxb[TBL];          // edge_idx * 128 (byte offset into history)

extern __shared__ unsigned char smem_raw[];

__device__ __forceinline__ void cp16(unsigned int saddr, const void* gptr) {
    asm volatile("cp.async.cg.shared.global [%0], [%1], 16;\n"
                 :: "r"(saddr), "l"(gptr));
}

__device__ __forceinline__ __half2 u2h2(unsigned int u) {
    __half2 h;
    *(unsigned int*)&h = u;
    return h;
}

// 32-bit shared-space loads (force LDS + single 32-bit address add)
__device__ __forceinline__ uint4 lds128(unsigned int a) {
    uint4 v;
    asm volatile("ld.shared.v4.b32 {%0,%1,%2,%3}, [%4];"
                 : "=r"(v.x), "=r"(v.y), "=r"(v.z), "=r"(v.w) : "r"(a));
    return v;
}
__device__ __forceinline__ __half2 ldsh2(unsigned int a) {
    unsigned int v;
    asm volatile("ld.shared.b32 %0, [%1];" : "=r"(v) : "r"(a));
    return u2h2(v);
}

// fast sigmoid via EX2+RCP (tanh.approx measured 60% SLOWER on sm_103a — do not use)
__device__ __forceinline__ float2 sigmoid2(float2 pre) {
    float2 s;
    s.x = __fdividef(1.0f, 1.0f + __expf(-pre.x));
    s.y = __fdividef(1.0f, 1.0f + __expf(-pre.y));
    return s;
}

// ---- prep: weights -> half, indices -> byte offsets ----
__global__ void prep_kernel(const float* __restrict__ weights,
                            const int*   __restrict__ edge_idx) {
    int i = blockIdx.x * blockDim.x + threadIdx.x;   // exactly TBL threads
    g_wh  [i] = __float2half(weights[i]);
    g_idxb[i] = edge_idx[i] << 7;                    // *128 bytes per history col
}

// 16-edge dot -> half2 partial (tree-reduced); ALL addressing 32-bit shared space.
// hlane32: s_base + lane*4 ; idx_a: addr of this w's 4x int4 ; wt_a: addr of 2x uint4
__device__ __forceinline__ __half2 pre_smem(unsigned int hlane32,
                                            unsigned int idx_a,
                                            unsigned int wt_a) {
    uint4 wq0 = lds128(wt_a);        // edges 0..7  (x=01 y=23 z=45 w=67)
    uint4 wq1 = lds128(wt_a + 16);   // edges 8..15
    __half2 z = __float2half2_rn(0.0f);
    __half2 acc0 = z, acc1 = z, acc2 = z, acc3 = z;
    #pragma unroll
    for (int g = 0; g < 4; ++g) {
        uint4 iv = lds128(idx_a + g * 16);
        unsigned int p0 = (g == 0) ? wq0.x : (g == 1) ? wq0.z : (g == 2) ? wq1.x : wq1.z;
        unsigned int p1 = (g == 0) ? wq0.y : (g == 1) ? wq0.w : (g == 2) ? wq1.y : wq1.w;
        __half2 wp0 = u2h2(p0);
        __half2 wp1 = u2h2(p1);
        acc0 = __hfma2(ldsh2(hlane32 + iv.x), __low2half2 (wp0), acc0);
        acc1 = __hfma2(ldsh2(hlane32 + iv.y), __high2half2(wp0), acc1);
        acc2 = __hfma2(ldsh2(hlane32 + iv.z), __low2half2 (wp1), acc2);
        acc3 = __hfma2(ldsh2(hlane32 + iv.w), __high2half2(wp1), acc3);
    }
    return __hadd2(__hadd2(acc0, acc1), __hadd2(acc2, acc3));
}

// layers 6,7: offsets may reach scratch -> branchless generic pointer select
__device__ __forceinline__ __half2 pre_mixed(const char* __restrict__ hlane,
                                             const char* __restrict__ glane,
                                             const int4* __restrict__ si4,
                                             const uint4* __restrict__ swq,
                                             int w) {
    const int LIM = SPLIT * 128;
    uint4 wq0 = swq[w * 2];
    uint4 wq1 = swq[w * 2 + 1];
    __half2 z = __float2half2_rn(0.0f);
    __half2 acc0 = z, acc1 = z, acc2 = z, acc3 = z;
    #pragma unroll
    for (int g = 0; g < 4; ++g) {
        int4 iv = si4[w * 4 + g];
        unsigned int p0 = (g == 0) ? wq0.x : (g == 1) ? wq0.z : (g == 2) ? wq1.x : wq1.z;
        unsigned int p1 = (g == 0) ? wq0.y : (g == 1) ? wq0.w : (g == 2) ? wq1.y : wq1.w;
        __half2 wp0 = u2h2(p0);
        __half2 wp1 = u2h2(p1);
        const char* px = ((iv.x < LIM) ? hlane : glane) + iv.x;
        const char* py = ((iv.y < LIM) ? hlane : glane) + iv.y;
        const char* pz = ((iv.z < LIM) ? hlane : glane) + iv.z;
        const char* pw = ((iv.w < LIM) ? hlane : glane) + iv.w;
        acc0 = __hfma2(*(const __half2*)px, __low2half2 (wp0), acc0);
        acc1 = __hfma2(*(const __half2*)py, __high2half2(wp0), acc1);
        acc2 = __hfma2(*(const __half2*)pz, __low2half2 (wp1), acc2);
        acc3 = __hfma2(*(const __half2*)pw, __high2half2(wp1), acc3);
    }
    return __hadd2(__hadd2(acc0, acc1), __hadd2(acc2, acc3));
}

// epilogue: half2 partial sum + fp32 bias -> sigmoid (fp32)
__device__ __forceinline__ float2 finish(__half2 hs, float bias) {
    float2 pre = __half22float2(hs);
    pre.x += bias;
    pre.y += bias;
    return sigmoid2(pre);
}

__global__ __launch_bounds__(NTHREADS, 1)
void ffn_edge_kernel(const float* __restrict__ inputs,    // [B, 128]
                     const float* __restrict__ biases,    // [L, W]
                     float*       __restrict__ out)       // [B, W]
{
    __half2* s_h2 = (__half2*)smem_raw;

    unsigned int s_base = (unsigned int)__cvta_generic_to_shared(smem_raw);

    const int tid  = threadIdx.x;
    const int lane = tid & 31;
    const int wid  = tid >> 5;
    const int row0 = blockIdx.x * T;

    __half2* gblk = g_scratch + (size_t)blockIdx.x * (SC_COLS * (T / 2));
    // 32-bit shared base for hot path; generic pointers only for mixed layers
    const unsigned int hlane32 = s_base + lane * 4;
    const char* hlane = (const char*)s_h2 + lane * 4;
    const char* glane = (const char*)gblk + lane * 4 - SPLIT * 128;

    // ---- Kick off layer-0 table prefetch into buf 0 (overlaps input staging) ----
    {
        unsigned int tb = s_base + OFF_TBL0;
        cp16(tb + TB_IDX + tid * 16, (const char*)g_idxb + tid * 16);           // 16 KB
        if (tid < 512) cp16(tb + TB_WT + tid * 16, (const char*)g_wh + tid * 16); // 8 KB
        if (tid < 64)  cp16(tb + TB_BIAS + tid * 16, (const char*)biases + tid * 16); // 1 KB
        asm volatile("cp.async.commit_group;\n");
    }

    // ---- Stage input [64][128] fp32 coalesced into pad-132 buffer.
    // Overlays hist bytes [16384, 50176) = cols 128..392 (< SPLIT, not yet written).
    float* s_stage = (float*)(smem_raw + 16384);
    {
        const float4* in4 = (const float4*)(inputs + (size_t)row0 * N_IN);
        #pragma unroll 1
        for (int i = tid; i < T * (N_IN / 4); i += NTHREADS) {
            int r  = i >> 5;            // 32 float4 per row
            int c4 = i & 31;
            float4 v = in4[i];
            float* dst = s_stage + r * 132 + c4 * 4;
            dst[0] = v.x; dst[1] = v.y; dst[2] = v.z; dst[3] = v.w;
        }
    }
    __syncthreads();
    // ---- Transpose-convert input into s_h2[col][pair]: lo = row 2p, hi = row 2p+1
    #pragma unroll 1
    for (int i = tid; i < N_IN * 32; i += NTHREADS) {
        int col = i >> 5;
        int p   = i & 31;
        float lo = s_stage[(2 * p)     * 132 + col];
        float hi = s_stage[(2 * p + 1) * 132 + col];
        s_h2[col * 32 + p] = __floats2half2_rn(lo, hi);
    }

    // ---- 8 layers; tables DOUBLE-buffered: prefetch next layer at top, overlap compute ----
    int ncols = N_IN;
    #pragma unroll 1
    for (int l = 0; l < NLAYERS; ++l) {
        asm volatile("cp.async.wait_group 0;\n");
        __syncthreads();   // tables buf[l&1] ready + prior-layer history (smem+gmem) visible

        // issue next layer's prefetch into the OTHER buffer (no one reads it now)
        if (l < NLAYERS - 1) {
            unsigned int tb = s_base + OFF_TBL0 + ((l + 1) & 1) * TBLBUF;
            const char* gi = (const char*)(g_idxb + (size_t)(l + 1) * WID * KK);
            const char* gw = (const char*)(g_wh   + (size_t)(l + 1) * WID * KK);
            cp16(tb + TB_IDX + tid * 16, gi + tid * 16);
            if (tid < 512) cp16(tb + TB_WT + tid * 16, gw + tid * 16);
            if (tid < 64)
                cp16(tb + TB_BIAS + tid * 16,
                     (const char*)(biases + (size_t)(l + 1) * WID) + tid * 16);
            asm volatile("cp.async.commit_group;\n");
        }

        const unsigned int tb32 = s_base + OFF_TBL0 + (l & 1) * TBLBUF;
        const unsigned char* tbl = smem_raw + OFF_TBL0 + (l & 1) * TBLBUF;
        const int4*  si4 = (const int4*) (tbl + TB_IDX);
        const uint4* swq = (const uint4*)(tbl + TB_WT);
        const float* sb  = (const float*)(tbl + TB_BIAS);

        if (l < 5) {
            // pure-SMEM gathers AND writes (layer 4 writes cols <= 1407 < SPLIT)
            #pragma unroll 2
            for (int w = wid; w < WID; w += NWARPS) {
                float2 sg = finish(pre_smem(hlane32, tb32 + TB_IDX + w * 64,
                                            tb32 + TB_WT + w * 32), sb[w]);
                s_h2[(ncols + w) * 32 + lane] = __floats2half2_rn(sg.x, sg.y);
            }
        } else if (l == 5) {
            // gathers pure-SMEM (cols < 1408); outputs (1408..1663) all to scratch
            #pragma unroll 2
            for (int w = wid; w < WID; w += NWARPS) {
                float2 sg = finish(pre_smem(hlane32, tb32 + TB_IDX + w * 64,
                                            tb32 + TB_WT + w * 32), sb[w]);
                gblk[(ncols + w - SPLIT) * 32 + lane] = __floats2half2_rn(sg.x, sg.y);
            }
        } else if (l == 6) {
            // mixed gathers; outputs (1664..1919) to scratch
            #pragma unroll 1
            for (int w = wid; w < WID; w += NWARPS) {
                float2 sg = finish(pre_mixed(hlane, glane, si4, swq, w), sb[w]);
                gblk[(ncols + w - SPLIT) * 32 + lane] = __floats2half2_rn(sg.x, sg.y);
            }
        } else {
            // layer 7: mixed gathers; fp32 result straight to GMEM
            float* og = out + ((size_t)row0 + 2 * lane) * WID;
            #pragma unroll 1
            for (int w = wid; w < WID; w += NWARPS) {
                float2 sg = finish(pre_mixed(hlane, glane, si4, swq, w), sb[w]);
                og[w]       = sg.x;   // row 2*lane
                og[w + WID] = sg.y;   // row 2*lane + 1
            }
        }
        ncols += WID;
    }
}

extern "C" void kernel_launch(void* const* d_in, const int* in_sizes, int n_in,
                              void* d_out, int out_size)
{
    (void)in_sizes; (void)n_in; (void)out_size;
    const float* inputs   = (const float*)d_in[0];
    const float* weights  = (const float*)d_in[1];
    const float* biases   = (const float*)d_in[2];
    const int*   edge_idx = (const int*)  d_in[3];
    float*       out      = (float*)d_out;

    cudaFuncSetAttribute(ffn_edge_kernel,
                         cudaFuncAttributeMaxDynamicSharedMemorySize, SMEM_BYTES);

    prep_kernel<<<TBL / 256, 256>>>(weights, edge_idx);

    dim3 grid(NBLOCKS);        // 512 blocks of 64 rows
    dim3 block(NTHREADS);
    ffn_edge_kernel<<<grid, block, SMEM_BYTES>>>(inputs, biases, out);
}